// round 15
// baseline (speedup 1.0000x reference)
#include <cuda_runtime.h>
#include <cuda_fp16.h>
#include <cstdint>

#define NPG     100
#define EPG     1600
#define HALF_E  800
#define DIMK    32
#define TPB     256
#define TILE_E  256
#define EPITCH  260
#define EPH     264     // half pitch for EtH
#define XPITCH  33
#define DPITCH  65
#define KSEL    800
#define MAXE    800000
#define NCHUNK  4

typedef unsigned long long ull;

__device__ __half g_ex[(size_t)MAXE * 64];
__device__ __half g_wa[(size_t)MAXE * 32];
__device__ float  g_p [(size_t)MAXE];

__device__ __forceinline__ ull dup2(float v) {
    ull r; asm("mov.b64 %0, {%1, %1};" : "=l"(r) : "f"(v)); return r;
}
__device__ __forceinline__ void fma2(ull& acc, ull a, ull b) {
    asm("fma.rn.f32x2 %0, %1, %2, %0;" : "+l"(acc) : "l"(a), "l"(b));
}
__device__ __forceinline__ float2 unp(ull v) {
    float2 f; asm("mov.b64 {%0, %1}, %2;" : "=f"(f.x), "=f"(f.y) : "l"(v)); return f;
}
__device__ __forceinline__ float fsig(float x) {
    return 1.0f / (1.0f + __expf(-x));
}

// ---- K1 SMEM layout (float idx) ----
#define S_XS    0        // 3304
#define S_WG    3304     // 2048  p1_w fp32
#define S_WH    5352     // 1536  (32x96 half: 64 lin1 | 32 wa)
#define S_BL1   6888     // 64
#define S_BWA   6952     // 32
#define S_BP1   6984     // 64
#define S_PB1O  7048     // 64
#define S_WP2   7112     // 64
#define S_PSA   7176     // 800
#define S_ET    7984     // 260*32 = 8320
#define S_ETH   16304    // 264*32 half = 4224 floats
#define K1_FLOATS 20528

extern "C" __global__ void __launch_bounds__(TPB, 2)
mgnn_k1(const float* __restrict__ x,
        const float* __restrict__ lin1_w, const float* __restrict__ lin1_b,
        const float* __restrict__ p1_w,   const float* __restrict__ p1_b,
        const float* __restrict__ p2_w,   const float* __restrict__ p2_b,
        const float* __restrict__ p_bias1,
        const float* __restrict__ wa_w,   const float* __restrict__ wa_b,
        const float* __restrict__ att,    const int* __restrict__ ei,
        int E, int graphBase)
{
    extern __shared__ float sm[];
    float*  xs    = sm + S_XS;
    float*  wG    = sm + S_WG;
    __half* wH    = (__half*)(sm + S_WH);
    float*  bl1S  = sm + S_BL1;
    float*  bwaS  = sm + S_BWA;
    float*  bp1S  = sm + S_BP1;
    float*  pb1oS = sm + S_PB1O;
    float*  wp2S  = sm + S_WP2;
    float*  psA   = sm + S_PSA;
    float*  Et    = sm + S_ET;
    __half* EtH   = (__half*)(sm + S_ETH);

    __shared__ float attS[64];

    const int tid = threadIdx.x;
    const int* srcA = ei;
    const int* tgtA = ei + E;

    const int item = graphBase * 2 + blockIdx.x;
    const int g = item >> 1;
    const int h = item & 1;
    const int nodeBase = g * NPG;
    const int edgeBase = g * EPG + h * HALF_E;

    // ---- stage weights / biases / x ----
    for (int idx = tid; idx < DIMK * 64; idx += TPB) wG[idx] = p1_w[idx];
    for (int idx = tid; idx < DIMK * 96; idx += TPB) {
        int k = idx / 96, n = idx % 96;
        float w = (n < 64) ? lin1_w[k * 64 + n] : wa_w[k * 32 + (n - 64)];
        wH[idx] = __float2half(w);
    }
    if (tid < 64) {
        bl1S[tid]  = lin1_b[tid];
        bp1S[tid]  = p1_b[tid];
        pb1oS[tid] = p_bias1[tid];
        wp2S[tid]  = p2_w[tid];
        attS[tid]  = att[tid];
    }
    if (tid < 32) bwaS[tid] = wa_b[tid];
    const float p2bias = p2_b[0];

    for (int idx = tid; idx < NPG * DIMK; idx += TPB) {
        int r = idx >> 5, c = idx & 31;
        xs[r * XPITCH + c] = x[(size_t)nodeBase * DIMK + idx];
    }
    for (int i = tid; i < HALF_E; i += TPB) psA[i] = 0.0f;
    __syncthreads();

    for (int tb = 0; tb < HALF_E; tb += TILE_E) {
        const int curE = min(TILE_E, HALF_E - tb);   // 256,256,256,32
        if (tid < curE) {
            int ge = edgeBase + tb + tid;
            int ls = srcA[ge] - nodeBase;
            int lt = tgtA[ge] - nodeBase;
            const float* xt = xs + lt * XPITCH;
            const float* xr = xs + ls * XPITCH;
            #pragma unroll
            for (int k = 0; k < DIMK; k++) {
                float e = xt[k] * xr[k];
                Et[k * EPITCH + tid]  = e;
                EtH[k * EPH + tid]    = __float2half(e);
            }
        }
        __syncthreads();

        const int nEg = curE >> 2;

        // ======== fp16 part: lin1 (64) | wa (32) via HFMA2 ========
        for (int u = tid; u < nEg * 12; u += TPB) {
            const int eg = u % nEg;
            const int cg = u / nEg;
            const int jc = cg * 8;      // 0..88

            __half2 acc[4][4];
            #pragma unroll
            for (int e = 0; e < 4; e++)
                #pragma unroll
                for (int q = 0; q < 4; q++)
                    acc[e][q] = __half2half2(__float2half(0.0f));

            const __half* etp = EtH + eg * 4;
            const __half* wp  = wH + jc;
            #pragma unroll 8
            for (int k = 0; k < DIMK; k++) {
                uint2 av = *(const uint2*)(etp + k * EPH);
                __half2 a01 = *(__half2*)&av.x;
                __half2 a23 = *(__half2*)&av.y;
                __half2 aa0 = __half2half2(__low2half(a01));
                __half2 aa1 = __half2half2(__high2half(a01));
                __half2 aa2 = __half2half2(__low2half(a23));
                __half2 aa3 = __half2half2(__high2half(a23));
                uint4 bv = *(const uint4*)(wp + k * 96);
                __half2 b0 = *(__half2*)&bv.x;
                __half2 b1 = *(__half2*)&bv.y;
                __half2 b2 = *(__half2*)&bv.z;
                __half2 b3 = *(__half2*)&bv.w;
                acc[0][0] = __hfma2(aa0, b0, acc[0][0]); acc[0][1] = __hfma2(aa0, b1, acc[0][1]);
                acc[0][2] = __hfma2(aa0, b2, acc[0][2]); acc[0][3] = __hfma2(aa0, b3, acc[0][3]);
                acc[1][0] = __hfma2(aa1, b0, acc[1][0]); acc[1][1] = __hfma2(aa1, b1, acc[1][1]);
                acc[1][2] = __hfma2(aa1, b2, acc[1][2]); acc[1][3] = __hfma2(aa1, b3, acc[1][3]);
                acc[2][0] = __hfma2(aa2, b0, acc[2][0]); acc[2][1] = __hfma2(aa2, b1, acc[2][1]);
                acc[2][2] = __hfma2(aa2, b2, acc[2][2]); acc[2][3] = __hfma2(aa2, b3, acc[2][3]);
                acc[3][0] = __hfma2(aa3, b0, acc[3][0]); acc[3][1] = __hfma2(aa3, b1, acc[3][1]);
                acc[3][2] = __hfma2(aa3, b2, acc[3][2]); acc[3][3] = __hfma2(aa3, b3, acc[3][3]);
            }

            const int iiBase = tb + eg * 4;
            if (jc < 64) {
                #pragma unroll
                for (int e = 0; e < 4; e++) {
                    unsigned hv[4];
                    #pragma unroll
                    for (int q = 0; q < 4; q++) {
                        float2 t2 = __half22float2(acc[e][q]);
                        float v0 = t2.x + bl1S[jc + 2 * q];
                        float v1 = t2.y + bl1S[jc + 2 * q + 1];
                        float c0 = attS[jc + 2 * q]     * fmaxf(v0, 0.0f);
                        float c1 = attS[jc + 2 * q + 1] * fmaxf(v1, 0.0f);
                        c0 = (c0 > 0.0f) ? c0 : 0.01f * c0;
                        c1 = (c1 > 0.0f) ? c1 : 0.01f * c1;
                        __half2 hh = __floats2half2_rn(__expf(c0), __expf(c1));
                        hv[q] = *(unsigned*)&hh;
                    }
                    uint4 pk; pk.x = hv[0]; pk.y = hv[1]; pk.z = hv[2]; pk.w = hv[3];
                    *(uint4*)(g_ex + (size_t)(edgeBase + iiBase + e) * 64 + jc) = pk;
                }
            } else {
                const int jj = jc - 64;
                #pragma unroll
                for (int e = 0; e < 4; e++) {
                    unsigned hv[4];
                    #pragma unroll
                    for (int q = 0; q < 4; q++) {
                        float2 t2 = __half22float2(acc[e][q]);
                        __half2 hh = __floats2half2_rn(t2.x + bwaS[jj + 2 * q],
                                                       t2.y + bwaS[jj + 2 * q + 1]);
                        hv[q] = *(unsigned*)&hh;
                    }
                    uint4 pk; pk.x = hv[0]; pk.y = hv[1]; pk.z = hv[2]; pk.w = hv[3];
                    *(uint4*)(g_wa + (size_t)(edgeBase + iiBase + e) * 32 + jj) = pk;
                }
            }
        }

        // ======== fp32 gate MLP (exact) ========
        for (int u = tid; u < nEg * 8; u += TPB) {
            const int eg = u % nEg;
            const int cg = u / nEg;
            const int jj = cg * 8;

            ull acc[4][4];
            {
                ulonglong2 b0 = *(const ulonglong2*)(bp1S + jj);
                ulonglong2 b1 = *(const ulonglong2*)(bp1S + jj + 4);
                #pragma unroll
                for (int e = 0; e < 4; e++) {
                    acc[e][0] = b0.x; acc[e][1] = b0.y;
                    acc[e][2] = b1.x; acc[e][3] = b1.y;
                }
            }
            const float* etp = Et + eg * 4;
            const float* wp  = wG + jj;
            #pragma unroll 8
            for (int k = 0; k < DIMK; k++) {
                float4 a4 = *(const float4*)(etp + k * EPITCH);
                ull a0 = dup2(a4.x), a1 = dup2(a4.y), a2 = dup2(a4.z), a3 = dup2(a4.w);
                ulonglong2 bA = *(const ulonglong2*)(wp + k * 64);
                ulonglong2 bB = *(const ulonglong2*)(wp + k * 64 + 4);
                fma2(acc[0][0], a0, bA.x); fma2(acc[0][1], a0, bA.y);
                fma2(acc[0][2], a0, bB.x); fma2(acc[0][3], a0, bB.y);
                fma2(acc[1][0], a1, bA.x); fma2(acc[1][1], a1, bA.y);
                fma2(acc[1][2], a1, bB.x); fma2(acc[1][3], a1, bB.y);
                fma2(acc[2][0], a2, bA.x); fma2(acc[2][1], a2, bA.y);
                fma2(acc[2][2], a2, bB.x); fma2(acc[2][3], a2, bB.y);
                fma2(acc[3][0], a3, bA.x); fma2(acc[3][1], a3, bA.y);
                fma2(acc[3][2], a3, bB.x); fma2(acc[3][3], a3, bB.y);
            }
            #pragma unroll
            for (int e = 0; e < 4; e++) {
                float s = 0.0f;
                #pragma unroll
                for (int q = 0; q < 4; q++) {
                    float2 v = unp(acc[e][q]);
                    s += (fmaxf(v.x, 0.0f) + pb1oS[jj + 2 * q])     * wp2S[jj + 2 * q];
                    s += (fmaxf(v.y, 0.0f) + pb1oS[jj + 2 * q + 1]) * wp2S[jj + 2 * q + 1];
                }
                atomicAdd(&psA[tb + eg * 4 + e], s);
            }
        }
        __syncthreads();
    }

    for (int i = tid; i < HALF_E; i += TPB)
        g_p[edgeBase + i] = fsig(psA[i] + p2bias);
}

// ================= K2: select + gathers (R8 measured-best) =================
#define K2_PS    0
#define K2_DENS  1600
#define K2_INVD  8104
#define K2_BOUT  8204
#define K2_CNT   8268
#define K2_OFFS  8368
#define K2_CUR   8472
#define K2_LIST  8572
#define K2_TIE   10172
#define K2_SCAL  10236
#define K2_UNI   10244
#define K2_FLOATS 13444

extern "C" __global__ void __launch_bounds__(TPB, 4)
mgnn_k2(const float* __restrict__ bias, const int* __restrict__ ei, int E,
        float* __restrict__ out, int graphBase)
{
    extern __shared__ float sm[];
    float* psA   = sm + K2_PS;
    float* dens  = sm + K2_DENS;
    float* invdS = sm + K2_INVD;
    float* boutS = sm + K2_BOUT;
    int*   cnt   = (int*)(sm + K2_CNT);
    int*   offs  = (int*)(sm + K2_OFFS);
    int*   curS  = (int*)(sm + K2_CUR);
    int*   listS = (int*)(sm + K2_LIST);
    int*   tieS  = (int*)(sm + K2_TIE);
    int*   scal  = (int*)(sm + K2_SCAL);
    int*   hist  = (int*)(sm + K2_UNI);
    float* als0  = sm + K2_UNI;
    float* als1  = sm + K2_UNI + EPG;

    const int g        = graphBase + blockIdx.x;
    const int tid      = threadIdx.x;
    const int nodeBase = g * NPG;
    const int edgeBase = g * EPG;
    const int* tgtA = ei + E;

    if (tid < 64) boutS[tid] = bias[tid];
    for (int t = tid; t < NPG; t += TPB) cnt[t] = 0;
    for (int i = tid; i < EPG; i += TPB) psA[i] = g_p[edgeBase + i];
    __syncthreads();
    for (int i = tid; i < EPG; i += TPB)
        atomicAdd(&cnt[tgtA[edgeBase + i] - nodeBase], 1);
    __syncthreads();

    if (tid < 32) {
        int base = tid * 4;
        int c0 = 0, c1 = 0, c2 = 0, c3 = 0;
        if (base < NPG) { c0 = cnt[base]; c1 = cnt[base+1]; c2 = cnt[base+2]; c3 = cnt[base+3]; }
        int s = c0 + c1 + c2 + c3;
        int ex = s;
        #pragma unroll
        for (int off = 1; off < 32; off <<= 1) {
            int v = __shfl_up_sync(0xFFFFFFFFu, ex, off);
            if (tid >= off) ex += v;
        }
        ex -= s;
        if (base < NPG) {
            offs[base]     = ex;
            offs[base + 1] = ex + c0;
            offs[base + 2] = ex + c0 + c1;
            offs[base + 3] = ex + c0 + c1 + c2;
            if (base + 4 == NPG) offs[NPG] = ex + s;
        }
    }
    __syncthreads();

    unsigned prefix = 0;
    int target = KSEL;
    for (int b = 3; b >= 0; b--) {
        for (int i = tid; i < 256; i += TPB) hist[i] = 0;
        __syncthreads();
        unsigned maskAbove = (b == 3) ? 0u : (0xFFFFFFFFu << (8 * (b + 1)));
        for (int i = tid; i < EPG; i += TPB) {
            unsigned ub = __float_as_uint(psA[i]);
            if ((ub & maskAbove) == (prefix & maskAbove))
                atomicAdd(&hist[(ub >> (8 * b)) & 255], 1);
        }
        __syncthreads();
        if (tid < 32) {
            const int hi = 255 - 8 * tid;
            int hh[8], s = 0;
            #pragma unroll
            for (int q = 0; q < 8; q++) { hh[q] = hist[hi - q]; s += hh[q]; }
            int ex = s;
            #pragma unroll
            for (int off = 1; off < 32; off <<= 1) {
                int v = __shfl_up_sync(0xFFFFFFFFu, ex, off);
                if (tid >= off) ex += v;
            }
            ex -= s;
            unsigned flags = __ballot_sync(0xFFFFFFFFu, ex + s >= target);
            int sel = (flags != 0u) ? (__ffs(flags) - 1) : 31;
            if (tid == sel) {
                int acc = ex, bin = hi - 7;
                #pragma unroll
                for (int q = 0; q < 8; q++) {
                    if (acc + hh[q] >= target) { bin = hi - q; break; }
                    acc += hh[q];
                }
                scal[0] = (int)(prefix | ((unsigned)bin << (8 * b)));
                scal[1] = target - acc;
            }
        }
        __syncthreads();
        prefix = (unsigned)scal[0];
        target = scal[1];
        __syncthreads();
    }
    const unsigned thrBits = prefix;

    if (tid == 0) { scal[2] = 0; scal[3] = 0; }
    __syncthreads();
    for (int i = tid; i < EPG; i += TPB) {
        unsigned ub = __float_as_uint(psA[i]);
        if (ub > thrBits) { atomicAdd(&scal[2], 1); }
        else if (ub == thrBits) {
            int pos = atomicAdd(&scal[3], 1);
            if (pos < 64) tieS[pos] = i;
        } else {
            psA[i] = 0.0f;
        }
    }
    __syncthreads();
    if (tid == 0) {
        int cGt = scal[2];
        int tn = min(scal[3], 64);
        int need = KSEL - cGt;
        for (int a = 1; a < tn; a++) {
            int v = tieS[a]; int bb = a - 1;
            while (bb >= 0 && tieS[bb] > v) { tieS[bb + 1] = tieS[bb]; bb--; }
            tieS[bb + 1] = v;
        }
        for (int r = need; r < tn; r++) if (r >= 0) psA[tieS[r]] = 0.0f;
    }
    __syncthreads();

    for (int t = tid; t < NPG; t += TPB) {
        curS[t] = offs[t];
        invdS[t] = 1.0f / fmaxf((float)cnt[t], 1.0f);
    }
    __syncthreads();
    for (int i = tid; i < EPG; i += TPB) {
        int lt = tgtA[edgeBase + i] - nodeBase;
        int pos = atomicAdd(&curS[lt], 1);
        listS[pos] = i;
    }
    __syncthreads();

    for (int u = tid; u < NPG * 8; u += TPB) {
        int t = u >> 3, ch = u & 7;
        int s0 = offs[t], s1 = offs[t + 1];
        float a[8] = {0, 0, 0, 0, 0, 0, 0, 0};
        int idx = s0;
        for (; idx + 3 < s1; idx += 4) {
            int i0 = listS[idx], i1 = listS[idx+1], i2 = listS[idx+2], i3 = listS[idx+3];
            uint4 h0 = *(const uint4*)(g_ex + (size_t)(edgeBase + i0) * 64 + ch * 8);
            uint4 h1 = *(const uint4*)(g_ex + (size_t)(edgeBase + i1) * 64 + ch * 8);
            uint4 h2 = *(const uint4*)(g_ex + (size_t)(edgeBase + i2) * 64 + ch * 8);
            uint4 h3 = *(const uint4*)(g_ex + (size_t)(edgeBase + i3) * 64 + ch * 8);
            const uint4* hs[4] = {&h0, &h1, &h2, &h3};
            #pragma unroll
            for (int r = 0; r < 4; r++) {
                float2 v0 = __half22float2(*(__half2*)&hs[r]->x);
                float2 v1 = __half22float2(*(__half2*)&hs[r]->y);
                float2 v2 = __half22float2(*(__half2*)&hs[r]->z);
                float2 v3 = __half22float2(*(__half2*)&hs[r]->w);
                a[0] += v0.x; a[1] += v0.y; a[2] += v1.x; a[3] += v1.y;
                a[4] += v2.x; a[5] += v2.y; a[6] += v3.x; a[7] += v3.y;
            }
        }
        for (; idx < s1; idx++) {
            int i = listS[idx];
            uint4 h4 = *(const uint4*)(g_ex + (size_t)(edgeBase + i) * 64 + ch * 8);
            float2 v0 = __half22float2(*(__half2*)&h4.x);
            float2 v1 = __half22float2(*(__half2*)&h4.y);
            float2 v2 = __half22float2(*(__half2*)&h4.z);
            float2 v3 = __half22float2(*(__half2*)&h4.w);
            a[0] += v0.x; a[1] += v0.y; a[2] += v1.x; a[3] += v1.y;
            a[4] += v2.x; a[5] += v2.y; a[6] += v3.x; a[7] += v3.y;
        }
        #pragma unroll
        for (int j = 0; j < 8; j++)
            dens[t * DPITCH + ch * 8 + j] = 1.0f / (a[j] + 1e-16f);
    }
    __syncthreads();

    for (int i = tid; i < EPG; i += TPB) {
        int lt = tgtA[edgeBase + i] - nodeBase;
        const float* invd = dens + lt * DPITCH;
        const uint4* exr = (const uint4*)(g_ex + (size_t)(edgeBase + i) * 64);
        float a0 = 0.0f, a1 = 0.0f;
        #pragma unroll
        for (int q = 0; q < 8; q++) {
            uint4 h4 = exr[q];
            float2 v0 = __half22float2(*(__half2*)&h4.x);
            float2 v1 = __half22float2(*(__half2*)&h4.y);
            float2 v2 = __half22float2(*(__half2*)&h4.z);
            float2 v3 = __half22float2(*(__half2*)&h4.w);
            const float* iv = invd + q * 8;
            float s = v0.x * iv[0] + v0.y * iv[1] + v1.x * iv[2] + v1.y * iv[3]
                    + v2.x * iv[4] + v2.y * iv[5] + v3.x * iv[6] + v3.y * iv[7];
            if (q < 4) a0 += s; else a1 += s;
        }
        float pv = psA[i];
        als0[i] = a0 * pv;
        als1[i] = a1 * pv;
    }
    __syncthreads();

    for (int u = tid; u < NPG * 8; u += TPB) {
        int t = u >> 3, ch = u & 7;
        const float* als = (ch >= 4) ? als1 : als0;
        int wcb = (ch & 3) * 8;
        int s0 = offs[t], s1 = offs[t + 1];
        float a[8] = {0, 0, 0, 0, 0, 0, 0, 0};
        int idx = s0;
        for (; idx + 3 < s1; idx += 4) {
            int i0 = listS[idx], i1 = listS[idx+1], i2 = listS[idx+2], i3 = listS[idx+3];
            uint4 h0 = *(const uint4*)(g_wa + (size_t)(edgeBase + i0) * 32 + wcb);
            uint4 h1 = *(const uint4*)(g_wa + (size_t)(edgeBase + i1) * 32 + wcb);
            uint4 h2 = *(const uint4*)(g_wa + (size_t)(edgeBase + i2) * 32 + wcb);
            uint4 h3 = *(const uint4*)(g_wa + (size_t)(edgeBase + i3) * 32 + wcb);
            float aps[4] = {als[i0], als[i1], als[i2], als[i3]};
            const uint4* hs[4] = {&h0, &h1, &h2, &h3};
            #pragma unroll
            for (int r = 0; r < 4; r++) {
                float2 w0 = __half22float2(*(__half2*)&hs[r]->x);
                float2 w1 = __half22float2(*(__half2*)&hs[r]->y);
                float2 w2 = __half22float2(*(__half2*)&hs[r]->z);
                float2 w3 = __half22float2(*(__half2*)&hs[r]->w);
                float ap = aps[r];
                a[0] += fsig(w0.x * ap); a[1] += fsig(w0.y * ap);
                a[2] += fsig(w1.x * ap); a[3] += fsig(w1.y * ap);
                a[4] += fsig(w2.x * ap); a[5] += fsig(w2.y * ap);
                a[6] += fsig(w3.x * ap); a[7] += fsig(w3.y * ap);
            }
        }
        for (; idx < s1; idx++) {
            int i = listS[idx];
            float ap = als[i];
            uint4 h4 = *(const uint4*)(g_wa + (size_t)(edgeBase + i) * 32 + wcb);
            float2 w0 = __half22float2(*(__half2*)&h4.x);
            float2 w1 = __half22float2(*(__half2*)&h4.y);
            float2 w2 = __half22float2(*(__half2*)&h4.z);
            float2 w3 = __half22float2(*(__half2*)&h4.w);
            a[0] += fsig(w0.x * ap); a[1] += fsig(w0.y * ap);
            a[2] += fsig(w1.x * ap); a[3] += fsig(w1.y * ap);
            a[4] += fsig(w2.x * ap); a[5] += fsig(w2.y * ap);
            a[6] += fsig(w3.x * ap); a[7] += fsig(w3.y * ap);
        }
        const float idg = invdS[t];
        const int ob = (nodeBase + t) * 64 + ch * 8;
        float4 o0, o1;
        o0.x = a[0] * idg + boutS[ch * 8 + 0];
        o0.y = a[1] * idg + boutS[ch * 8 + 1];
        o0.z = a[2] * idg + boutS[ch * 8 + 2];
        o0.w = a[3] * idg + boutS[ch * 8 + 3];
        o1.x = a[4] * idg + boutS[ch * 8 + 4];
        o1.y = a[5] * idg + boutS[ch * 8 + 5];
        o1.z = a[6] * idg + boutS[ch * 8 + 6];
        o1.w = a[7] * idg + boutS[ch * 8 + 7];
        *(float4*)(out + ob)     = o0;
        *(float4*)(out + ob + 4) = o1;
    }
}

extern "C" void kernel_launch(void* const* d_in, const int* in_sizes, int n_in,
                              void* d_out, int out_size)
{
    const float* x       = (const float*)d_in[0];
    const float* lin1_w  = (const float*)d_in[1];
    const float* lin1_b  = (const float*)d_in[2];
    const float* p1_w    = (const float*)d_in[3];
    const float* p1_b    = (const float*)d_in[4];
    const float* p2_w    = (const float*)d_in[5];
    const float* p2_b    = (const float*)d_in[6];
    const float* p_bias1 = (const float*)d_in[7];
    const float* wa_w    = (const float*)d_in[9];
    const float* wa_b    = (const float*)d_in[10];
    const float* att     = (const float*)d_in[11];
    const float* bias    = (const float*)d_in[12];
    const int*   ei      = (const int*)d_in[13];
    float* out = (float*)d_out;

    const int E = in_sizes[13] / 2;
    const int B = E / EPG;

    const size_t smem1 = (size_t)K1_FLOATS * 4;
    const size_t smem2 = (size_t)K2_FLOATS * 4;
    cudaFuncSetAttribute(mgnn_k1, cudaFuncAttributeMaxDynamicSharedMemorySize, (int)smem1);
    cudaFuncSetAttribute(mgnn_k2, cudaFuncAttributeMaxDynamicSharedMemorySize, (int)smem2);

    // Forked-capture pipeline: main stream runs K1 chunks; s2 runs K2 chunks,
    // each gated on its K1 chunk's event; joined back at the end.
    cudaStream_t s2;
    cudaStreamCreateWithFlags(&s2, cudaStreamNonBlocking);
    cudaEvent_t ev[NCHUNK + 1];
    for (int i = 0; i <= NCHUNK; i++)
        cudaEventCreateWithFlags(&ev[i], cudaEventDisableTiming);

    const int gs = (B + NCHUNK - 1) / NCHUNK;
    for (int c = 0; c < NCHUNK; c++) {
        int g0 = c * gs;
        int g1 = (g0 + gs < B) ? (g0 + gs) : B;
        if (g0 >= g1) continue;
        mgnn_k1<<<2 * (g1 - g0), TPB, smem1>>>(x, lin1_w, lin1_b, p1_w, p1_b,
                                               p2_w, p2_b, p_bias1, wa_w, wa_b,
                                               att, ei, E, g0);
        cudaEventRecord(ev[c], 0);
        cudaStreamWaitEvent(s2, ev[c], 0);
        mgnn_k2<<<g1 - g0, TPB, smem2, s2>>>(bias, ei, E, out, g0);
    }
    cudaEventRecord(ev[NCHUNK], s2);
    cudaStreamWaitEvent(0, ev[NCHUNK], 0);

    cudaStreamDestroy(s2);
    for (int i = 0; i <= NCHUNK; i++) cudaEventDestroy(ev[i]);
}

// round 16
// speedup vs baseline: 1.4807x; 1.4807x over previous
#include <cuda_runtime.h>
#include <cuda_fp16.h>
#include <cstdint>

#define NPG     100
#define EPG     1600
#define HALF_E  800
#define DIMK    32
#define TPB     256
#define TILE_E  256
#define EPITCH  260
#define EPH     264     // half pitch for EtH
#define XPITCH  33
#define KSEL    800
#define MAXE    800000
#define K1_GRID 296

typedef unsigned long long ull;

__device__ __half g_ex[(size_t)MAXE * 64];
__device__ __half g_wa[(size_t)MAXE * 32];
__device__ float  g_p [(size_t)MAXE];
__device__ int    g_ctr;   // zero-init; K2 resets for next replay

__device__ __forceinline__ ull dup2(float v) {
    ull r; asm("mov.b64 %0, {%1, %1};" : "=l"(r) : "f"(v)); return r;
}
__device__ __forceinline__ void fma2(ull& acc, ull a, ull b) {
    asm("fma.rn.f32x2 %0, %1, %2, %0;" : "+l"(acc) : "l"(a), "l"(b));
}
__device__ __forceinline__ float2 unp(ull v) {
    float2 f; asm("mov.b64 {%0, %1}, %2;" : "=f"(f.x), "=f"(f.y) : "l"(v)); return f;
}
__device__ __forceinline__ float fsig(float x) {
    return 1.0f / (1.0f + __expf(-x));
}

// ---- K1 SMEM layout (float idx) ----
#define S_XS    0        // 3304
#define S_WG    3304     // 2048  p1_w fp32
#define S_WH    5352     // 1536  (32x96 half: 64 lin1 | 32 wa)
#define S_BL1   6888     // 64
#define S_BWA   6952     // 32
#define S_BP1   6984     // 64
#define S_PB1O  7048     // 64
#define S_WP2   7112     // 64
#define S_PSA   7176     // 800
#define S_ITEM  7976     // 8
#define S_ET    7984     // 260*32 = 8320
#define S_ETH   16304    // 264*32 half = 4224 floats
#define K1_FLOATS 20528

extern "C" __global__ void __launch_bounds__(TPB, 2)
mgnn_k1(const float* __restrict__ x,
        const float* __restrict__ lin1_w, const float* __restrict__ lin1_b,
        const float* __restrict__ p1_w,   const float* __restrict__ p1_b,
        const float* __restrict__ p2_w,   const float* __restrict__ p2_b,
        const float* __restrict__ p_bias1,
        const float* __restrict__ wa_w,   const float* __restrict__ wa_b,
        const float* __restrict__ att,    const int* __restrict__ ei,
        int E, int nItems)
{
    extern __shared__ float sm[];
    float*  xs    = sm + S_XS;
    float*  wG    = sm + S_WG;
    __half* wH    = (__half*)(sm + S_WH);
    float*  bl1S  = sm + S_BL1;
    float*  bwaS  = sm + S_BWA;
    float*  bp1S  = sm + S_BP1;
    float*  pb1oS = sm + S_PB1O;
    float*  wp2S  = sm + S_WP2;
    float*  psA   = sm + S_PSA;
    int*    itemS = (int*)(sm + S_ITEM);
    float*  Et    = sm + S_ET;
    __half* EtH   = (__half*)(sm + S_ETH);

    __shared__ float attS[64];

    const int tid = threadIdx.x;
    const int* srcA = ei;
    const int* tgtA = ei + E;

    for (int idx = tid; idx < DIMK * 64; idx += TPB) wG[idx] = p1_w[idx];
    for (int idx = tid; idx < DIMK * 96; idx += TPB) {
        int k = idx / 96, n = idx % 96;
        float w = (n < 64) ? lin1_w[k * 64 + n] : wa_w[k * 32 + (n - 64)];
        wH[idx] = __float2half(w);
    }
    if (tid < 64) {
        bl1S[tid]  = lin1_b[tid];
        bp1S[tid]  = p1_b[tid];
        pb1oS[tid] = p_bias1[tid];
        wp2S[tid]  = p2_w[tid];
        attS[tid]  = att[tid];
    }
    if (tid < 32) bwaS[tid] = wa_b[tid];
    const float p2bias = p2_b[0];

    while (true) {
        if (tid == 0) itemS[0] = atomicAdd(&g_ctr, 1);
        __syncthreads();
        const int item = itemS[0];
        __syncthreads();
        if (item >= nItems) break;

        const int g = item >> 1;
        const int h = item & 1;
        const int nodeBase = g * NPG;
        const int edgeBase = g * EPG + h * HALF_E;

        for (int idx = tid; idx < NPG * DIMK; idx += TPB) {
            int r = idx >> 5, c = idx & 31;
            xs[r * XPITCH + c] = x[(size_t)nodeBase * DIMK + idx];
        }
        for (int i = tid; i < HALF_E; i += TPB) psA[i] = 0.0f;
        __syncthreads();

        for (int tb = 0; tb < HALF_E; tb += TILE_E) {
            const int curE = min(TILE_E, HALF_E - tb);   // 256,256,256,32
            if (tid < curE) {
                int ge = edgeBase + tb + tid;
                int ls = srcA[ge] - nodeBase;
                int lt = tgtA[ge] - nodeBase;
                const float* xt = xs + lt * XPITCH;
                const float* xr = xs + ls * XPITCH;
                #pragma unroll
                for (int k = 0; k < DIMK; k++) {
                    float e = xt[k] * xr[k];
                    Et[k * EPITCH + tid]  = e;
                    EtH[k * EPH + tid]    = __float2half(e);
                }
            }
            __syncthreads();

            const int nEg = curE >> 2;

            // ======== fp16 part: lin1 (64) | wa (32) via HFMA2 ========
            for (int u = tid; u < nEg * 12; u += TPB) {
                const int eg = u % nEg;
                const int cg = u / nEg;
                const int jc = cg * 8;

                __half2 acc[4][4];
                #pragma unroll
                for (int e = 0; e < 4; e++)
                    #pragma unroll
                    for (int q = 0; q < 4; q++)
                        acc[e][q] = __half2half2(__float2half(0.0f));

                const __half* etp = EtH + eg * 4;
                const __half* wp  = wH + jc;
                #pragma unroll 8
                for (int k = 0; k < DIMK; k++) {
                    uint2 av = *(const uint2*)(etp + k * EPH);
                    __half2 a01 = *(__half2*)&av.x;
                    __half2 a23 = *(__half2*)&av.y;
                    __half2 aa0 = __half2half2(__low2half(a01));
                    __half2 aa1 = __half2half2(__high2half(a01));
                    __half2 aa2 = __half2half2(__low2half(a23));
                    __half2 aa3 = __half2half2(__high2half(a23));
                    uint4 bv = *(const uint4*)(wp + k * 96);
                    __half2 b0 = *(__half2*)&bv.x;
                    __half2 b1 = *(__half2*)&bv.y;
                    __half2 b2 = *(__half2*)&bv.z;
                    __half2 b3 = *(__half2*)&bv.w;
                    acc[0][0] = __hfma2(aa0, b0, acc[0][0]); acc[0][1] = __hfma2(aa0, b1, acc[0][1]);
                    acc[0][2] = __hfma2(aa0, b2, acc[0][2]); acc[0][3] = __hfma2(aa0, b3, acc[0][3]);
                    acc[1][0] = __hfma2(aa1, b0, acc[1][0]); acc[1][1] = __hfma2(aa1, b1, acc[1][1]);
                    acc[1][2] = __hfma2(aa1, b2, acc[1][2]); acc[1][3] = __hfma2(aa1, b3, acc[1][3]);
                    acc[2][0] = __hfma2(aa2, b0, acc[2][0]); acc[2][1] = __hfma2(aa2, b1, acc[2][1]);
                    acc[2][2] = __hfma2(aa2, b2, acc[2][2]); acc[2][3] = __hfma2(aa2, b3, acc[2][3]);
                    acc[3][0] = __hfma2(aa3, b0, acc[3][0]); acc[3][1] = __hfma2(aa3, b1, acc[3][1]);
                    acc[3][2] = __hfma2(aa3, b2, acc[3][2]); acc[3][3] = __hfma2(aa3, b3, acc[3][3]);
                }

                const int iiBase = tb + eg * 4;
                if (jc < 64) {
                    #pragma unroll
                    for (int e = 0; e < 4; e++) {
                        unsigned hv[4];
                        #pragma unroll
                        for (int q = 0; q < 4; q++) {
                            float2 t2 = __half22float2(acc[e][q]);
                            float v0 = t2.x + bl1S[jc + 2 * q];
                            float v1 = t2.y + bl1S[jc + 2 * q + 1];
                            float c0 = attS[jc + 2 * q]     * fmaxf(v0, 0.0f);
                            float c1 = attS[jc + 2 * q + 1] * fmaxf(v1, 0.0f);
                            c0 = (c0 > 0.0f) ? c0 : 0.01f * c0;
                            c1 = (c1 > 0.0f) ? c1 : 0.01f * c1;
                            __half2 hh = __floats2half2_rn(__expf(c0), __expf(c1));
                            hv[q] = *(unsigned*)&hh;
                        }
                        uint4 pk; pk.x = hv[0]; pk.y = hv[1]; pk.z = hv[2]; pk.w = hv[3];
                        *(uint4*)(g_ex + (size_t)(edgeBase + iiBase + e) * 64 + jc) = pk;
                    }
                } else {
                    const int jj = jc - 64;
                    #pragma unroll
                    for (int e = 0; e < 4; e++) {
                        unsigned hv[4];
                        #pragma unroll
                        for (int q = 0; q < 4; q++) {
                            float2 t2 = __half22float2(acc[e][q]);
                            __half2 hh = __floats2half2_rn(t2.x + bwaS[jj + 2 * q],
                                                           t2.y + bwaS[jj + 2 * q + 1]);
                            hv[q] = *(unsigned*)&hh;
                        }
                        uint4 pk; pk.x = hv[0]; pk.y = hv[1]; pk.z = hv[2]; pk.w = hv[3];
                        *(uint4*)(g_wa + (size_t)(edgeBase + iiBase + e) * 32 + jj) = pk;
                    }
                }
            }

            // ======== fp32 gate MLP (exact) ========
            for (int u = tid; u < nEg * 8; u += TPB) {
                const int eg = u % nEg;
                const int cg = u / nEg;
                const int jj = cg * 8;

                ull acc[4][4];
                {
                    ulonglong2 b0 = *(const ulonglong2*)(bp1S + jj);
                    ulonglong2 b1 = *(const ulonglong2*)(bp1S + jj + 4);
                    #pragma unroll
                    for (int e = 0; e < 4; e++) {
                        acc[e][0] = b0.x; acc[e][1] = b0.y;
                        acc[e][2] = b1.x; acc[e][3] = b1.y;
                    }
                }
                const float* etp = Et + eg * 4;
                const float* wp  = wG + jj;
                #pragma unroll 8
                for (int k = 0; k < DIMK; k++) {
                    float4 a4 = *(const float4*)(etp + k * EPITCH);
                    ull a0 = dup2(a4.x), a1 = dup2(a4.y), a2 = dup2(a4.z), a3 = dup2(a4.w);
                    ulonglong2 bA = *(const ulonglong2*)(wp + k * 64);
                    ulonglong2 bB = *(const ulonglong2*)(wp + k * 64 + 4);
                    fma2(acc[0][0], a0, bA.x); fma2(acc[0][1], a0, bA.y);
                    fma2(acc[0][2], a0, bB.x); fma2(acc[0][3], a0, bB.y);
                    fma2(acc[1][0], a1, bA.x); fma2(acc[1][1], a1, bA.y);
                    fma2(acc[1][2], a1, bB.x); fma2(acc[1][3], a1, bB.y);
                    fma2(acc[2][0], a2, bA.x); fma2(acc[2][1], a2, bA.y);
                    fma2(acc[2][2], a2, bB.x); fma2(acc[2][3], a2, bB.y);
                    fma2(acc[3][0], a3, bA.x); fma2(acc[3][1], a3, bA.y);
                    fma2(acc[3][2], a3, bB.x); fma2(acc[3][3], a3, bB.y);
                }
                #pragma unroll
                for (int e = 0; e < 4; e++) {
                    float s = 0.0f;
                    #pragma unroll
                    for (int q = 0; q < 4; q++) {
                        float2 v = unp(acc[e][q]);
                        s += (fmaxf(v.x, 0.0f) + pb1oS[jj + 2 * q])     * wp2S[jj + 2 * q];
                        s += (fmaxf(v.y, 0.0f) + pb1oS[jj + 2 * q + 1]) * wp2S[jj + 2 * q + 1];
                    }
                    atomicAdd(&psA[tb + eg * 4 + e], s);
                }
            }
            __syncthreads();
        }

        for (int i = tid; i < HALF_E; i += TPB)
            g_p[edgeBase + i] = fsig(psA[i] + p2bias);
        __syncthreads();
    }
}

// ================= K2: select + fused den/alpha + msg =================
#define K2_PS    0       // 1600
#define K2_INVD  1600    // 100
#define K2_BOUT  1700    // 64
#define K2_CNT   1764    // 100 (int)
#define K2_OFFS  1864    // 104 (int)
#define K2_CUR   1968    // 100 (int)
#define K2_LIST  2068    // 1600 (int)
#define K2_TIE   3668    // 64 (int)
#define K2_SCAL  3732    // 12 (int)
#define K2_UNI   3744    // union: hist 256 / als0+als1 3200
#define K2_FLOATS 6944

extern "C" __global__ void __launch_bounds__(TPB, 4)
mgnn_k2(const float* __restrict__ bias, const int* __restrict__ ei, int E,
        float* __restrict__ out)
{
    extern __shared__ float sm[];
    float* psA   = sm + K2_PS;
    float* invdS = sm + K2_INVD;
    float* boutS = sm + K2_BOUT;
    int*   cnt   = (int*)(sm + K2_CNT);
    int*   offs  = (int*)(sm + K2_OFFS);
    int*   curS  = (int*)(sm + K2_CUR);
    int*   listS = (int*)(sm + K2_LIST);
    int*   tieS  = (int*)(sm + K2_TIE);
    int*   scal  = (int*)(sm + K2_SCAL);
    int*   hist  = (int*)(sm + K2_UNI);
    float* als0  = sm + K2_UNI;
    float* als1  = sm + K2_UNI + EPG;

    const int g        = blockIdx.x;
    const int tid      = threadIdx.x;
    const int nodeBase = g * NPG;
    const int edgeBase = g * EPG;
    const int* tgtA = ei + E;

    if (g == 0 && tid == 0) g_ctr = 0;   // reset K1 work queue for next replay

    if (tid < 64) boutS[tid] = bias[tid];
    for (int t = tid; t < NPG; t += TPB) cnt[t] = 0;
    for (int i = tid; i < EPG; i += TPB) psA[i] = g_p[edgeBase + i];
    __syncthreads();
    for (int i = tid; i < EPG; i += TPB)
        atomicAdd(&cnt[tgtA[edgeBase + i] - nodeBase], 1);
    __syncthreads();

    // ---- CSR offsets (warp prefix) ----
    if (tid < 32) {
        int base = tid * 4;
        int c0 = 0, c1 = 0, c2 = 0, c3 = 0;
        if (base < NPG) { c0 = cnt[base]; c1 = cnt[base+1]; c2 = cnt[base+2]; c3 = cnt[base+3]; }
        int s = c0 + c1 + c2 + c3;
        int ex = s;
        #pragma unroll
        for (int off = 1; off < 32; off <<= 1) {
            int v = __shfl_up_sync(0xFFFFFFFFu, ex, off);
            if (tid >= off) ex += v;
        }
        ex -= s;
        if (base < NPG) {
            offs[base]     = ex;
            offs[base + 1] = ex + c0;
            offs[base + 2] = ex + c0 + c1;
            offs[base + 3] = ex + c0 + c1 + c2;
            if (base + 4 == NPG) offs[NPG] = ex + s;
        }
    }
    __syncthreads();

    // ---- radix select: 800th largest p ----
    unsigned prefix = 0;
    int target = KSEL;
    for (int b = 3; b >= 0; b--) {
        for (int i = tid; i < 256; i += TPB) hist[i] = 0;
        __syncthreads();
        unsigned maskAbove = (b == 3) ? 0u : (0xFFFFFFFFu << (8 * (b + 1)));
        for (int i = tid; i < EPG; i += TPB) {
            unsigned ub = __float_as_uint(psA[i]);
            if ((ub & maskAbove) == (prefix & maskAbove))
                atomicAdd(&hist[(ub >> (8 * b)) & 255], 1);
        }
        __syncthreads();
        if (tid < 32) {
            const int hi = 255 - 8 * tid;
            int hh[8], s = 0;
            #pragma unroll
            for (int q = 0; q < 8; q++) { hh[q] = hist[hi - q]; s += hh[q]; }
            int ex = s;
            #pragma unroll
            for (int off = 1; off < 32; off <<= 1) {
                int v = __shfl_up_sync(0xFFFFFFFFu, ex, off);
                if (tid >= off) ex += v;
            }
            ex -= s;
            unsigned flags = __ballot_sync(0xFFFFFFFFu, ex + s >= target);
            int sel = (flags != 0u) ? (__ffs(flags) - 1) : 31;
            if (tid == sel) {
                int acc = ex, bin = hi - 7;
                #pragma unroll
                for (int q = 0; q < 8; q++) {
                    if (acc + hh[q] >= target) { bin = hi - q; break; }
                    acc += hh[q];
                }
                scal[0] = (int)(prefix | ((unsigned)bin << (8 * b)));
                scal[1] = target - acc;
            }
        }
        __syncthreads();
        prefix = (unsigned)scal[0];
        target = scal[1];
        __syncthreads();
    }
    const unsigned thrBits = prefix;

    if (tid == 0) { scal[2] = 0; scal[3] = 0; }
    __syncthreads();
    for (int i = tid; i < EPG; i += TPB) {
        unsigned ub = __float_as_uint(psA[i]);
        if (ub > thrBits) { atomicAdd(&scal[2], 1); }
        else if (ub == thrBits) {
            int pos = atomicAdd(&scal[3], 1);
            if (pos < 64) tieS[pos] = i;
        } else {
            psA[i] = 0.0f;
        }
    }
    __syncthreads();
    if (tid == 0) {
        int cGt = scal[2];
        int tn = min(scal[3], 64);
        int need = KSEL - cGt;
        for (int a = 1; a < tn; a++) {
            int v = tieS[a]; int bb = a - 1;
            while (bb >= 0 && tieS[bb] > v) { tieS[bb + 1] = tieS[bb]; bb--; }
            tieS[bb + 1] = v;
        }
        for (int r = need; r < tn; r++) if (r >= 0) psA[tieS[r]] = 0.0f;
    }
    __syncthreads();

    // ---- CSR scatter + invdeg ----
    for (int t = tid; t < NPG; t += TPB) {
        curS[t] = offs[t];
        invdS[t] = 1.0f / fmaxf((float)cnt[t], 1.0f);
    }
    __syncthreads();
    for (int i = tid; i < EPG; i += TPB) {
        int lt = tgtA[edgeBase + i] - nodeBase;
        int pos = atomicAdd(&curS[lt], 1);
        listS[pos] = i;
    }
    __syncthreads();

    // ---- zero als (overwrites hist union) ----
    for (int i = tid; i < 2 * EPG; i += TPB) als0[i] = 0.0f;
    __syncthreads();

    // ---- fused den + alpha: unit = (target, 8-col chunk) ----
    for (int u = tid; u < NPG * 8; u += TPB) {
        int t = u >> 3, ch = u & 7;
        float* als = (ch >= 4) ? als1 : als0;
        int s0 = offs[t], s1 = offs[t + 1];
        float a[8] = {0, 0, 0, 0, 0, 0, 0, 0};
        int idx = s0;
        for (; idx + 3 < s1; idx += 4) {
            int i0 = listS[idx], i1 = listS[idx+1], i2 = listS[idx+2], i3 = listS[idx+3];
            uint4 h0 = *(const uint4*)(g_ex + (size_t)(edgeBase + i0) * 64 + ch * 8);
            uint4 h1 = *(const uint4*)(g_ex + (size_t)(edgeBase + i1) * 64 + ch * 8);
            uint4 h2 = *(const uint4*)(g_ex + (size_t)(edgeBase + i2) * 64 + ch * 8);
            uint4 h3 = *(const uint4*)(g_ex + (size_t)(edgeBase + i3) * 64 + ch * 8);
            const uint4* hs[4] = {&h0, &h1, &h2, &h3};
            #pragma unroll
            for (int r = 0; r < 4; r++) {
                float2 v0 = __half22float2(*(__half2*)&hs[r]->x);
                float2 v1 = __half22float2(*(__half2*)&hs[r]->y);
                float2 v2 = __half22float2(*(__half2*)&hs[r]->z);
                float2 v3 = __half22float2(*(__half2*)&hs[r]->w);
                a[0] += v0.x; a[1] += v0.y; a[2] += v1.x; a[3] += v1.y;
                a[4] += v2.x; a[5] += v2.y; a[6] += v3.x; a[7] += v3.y;
            }
        }
        for (; idx < s1; idx++) {
            int i = listS[idx];
            uint4 h4 = *(const uint4*)(g_ex + (size_t)(edgeBase + i) * 64 + ch * 8);
            float2 v0 = __half22float2(*(__half2*)&h4.x);
            float2 v1 = __half22float2(*(__half2*)&h4.y);
            float2 v2 = __half22float2(*(__half2*)&h4.z);
            float2 v3 = __half22float2(*(__half2*)&h4.w);
            a[0] += v0.x; a[1] += v0.y; a[2] += v1.x; a[3] += v1.y;
            a[4] += v2.x; a[5] += v2.y; a[6] += v3.x; a[7] += v3.y;
        }
        float iv[8];
        #pragma unroll
        for (int j = 0; j < 8; j++) iv[j] = 1.0f / (a[j] + 1e-16f);

        // re-walk (rows L1-resident): partial alpha = sum_{j in chunk} ex*invd
        for (idx = s0; idx < s1; idx++) {
            int i = listS[idx];
            uint4 h4 = *(const uint4*)(g_ex + (size_t)(edgeBase + i) * 64 + ch * 8);
            float2 v0 = __half22float2(*(__half2*)&h4.x);
            float2 v1 = __half22float2(*(__half2*)&h4.y);
            float2 v2 = __half22float2(*(__half2*)&h4.z);
            float2 v3 = __half22float2(*(__half2*)&h4.w);
            float s = v0.x * iv[0] + v0.y * iv[1] + v1.x * iv[2] + v1.y * iv[3]
                    + v2.x * iv[4] + v2.y * iv[5] + v3.x * iv[6] + v3.y * iv[7];
            atomicAdd(&als[i], s);
        }
    }
    __syncthreads();

    // ---- message gather + output ----
    for (int u = tid; u < NPG * 8; u += TPB) {
        int t = u >> 3, ch = u & 7;
        const float* als = (ch >= 4) ? als1 : als0;
        int wcb = (ch & 3) * 8;
        int s0 = offs[t], s1 = offs[t + 1];
        float a[8] = {0, 0, 0, 0, 0, 0, 0, 0};
        int idx = s0;
        for (; idx + 3 < s1; idx += 4) {
            int i0 = listS[idx], i1 = listS[idx+1], i2 = listS[idx+2], i3 = listS[idx+3];
            uint4 h0 = *(const uint4*)(g_wa + (size_t)(edgeBase + i0) * 32 + wcb);
            uint4 h1 = *(const uint4*)(g_wa + (size_t)(edgeBase + i1) * 32 + wcb);
            uint4 h2 = *(const uint4*)(g_wa + (size_t)(edgeBase + i2) * 32 + wcb);
            uint4 h3 = *(const uint4*)(g_wa + (size_t)(edgeBase + i3) * 32 + wcb);
            float aps[4] = {als[i0] * psA[i0], als[i1] * psA[i1],
                            als[i2] * psA[i2], als[i3] * psA[i3]};
            const uint4* hs[4] = {&h0, &h1, &h2, &h3};
            #pragma unroll
            for (int r = 0; r < 4; r++) {
                float2 w0 = __half22float2(*(__half2*)&hs[r]->x);
                float2 w1 = __half22float2(*(__half2*)&hs[r]->y);
                float2 w2 = __half22float2(*(__half2*)&hs[r]->z);
                float2 w3 = __half22float2(*(__half2*)&hs[r]->w);
                float ap = aps[r];
                a[0] += fsig(w0.x * ap); a[1] += fsig(w0.y * ap);
                a[2] += fsig(w1.x * ap); a[3] += fsig(w1.y * ap);
                a[4] += fsig(w2.x * ap); a[5] += fsig(w2.y * ap);
                a[6] += fsig(w3.x * ap); a[7] += fsig(w3.y * ap);
            }
        }
        for (; idx < s1; idx++) {
            int i = listS[idx];
            float ap = als[i] * psA[i];
            uint4 h4 = *(const uint4*)(g_wa + (size_t)(edgeBase + i) * 32 + wcb);
            float2 w0 = __half22float2(*(__half2*)&h4.x);
            float2 w1 = __half22float2(*(__half2*)&h4.y);
            float2 w2 = __half22float2(*(__half2*)&h4.z);
            float2 w3 = __half22float2(*(__half2*)&h4.w);
            a[0] += fsig(w0.x * ap); a[1] += fsig(w0.y * ap);
            a[2] += fsig(w1.x * ap); a[3] += fsig(w1.y * ap);
            a[4] += fsig(w2.x * ap); a[5] += fsig(w2.y * ap);
            a[6] += fsig(w3.x * ap); a[7] += fsig(w3.y * ap);
        }
        const float idg = invdS[t];
        const int ob = (nodeBase + t) * 64 + ch * 8;
        float4 o0, o1;
        o0.x = a[0] * idg + boutS[ch * 8 + 0];
        o0.y = a[1] * idg + boutS[ch * 8 + 1];
        o0.z = a[2] * idg + boutS[ch * 8 + 2];
        o0.w = a[3] * idg + boutS[ch * 8 + 3];
        o1.x = a[4] * idg + boutS[ch * 8 + 4];
        o1.y = a[5] * idg + boutS[ch * 8 + 5];
        o1.z = a[6] * idg + boutS[ch * 8 + 6];
        o1.w = a[7] * idg + boutS[ch * 8 + 7];
        *(float4*)(out + ob)     = o0;
        *(float4*)(out + ob + 4) = o1;
    }
}

extern "C" void kernel_launch(void* const* d_in, const int* in_sizes, int n_in,
                              void* d_out, int out_size)
{
    const float* x       = (const float*)d_in[0];
    const float* lin1_w  = (const float*)d_in[1];
    const float* lin1_b  = (const float*)d_in[2];
    const float* p1_w    = (const float*)d_in[3];
    const float* p1_b    = (const float*)d_in[4];
    const float* p2_w    = (const float*)d_in[5];
    const float* p2_b    = (const float*)d_in[6];
    const float* p_bias1 = (const float*)d_in[7];
    const float* wa_w    = (const float*)d_in[9];
    const float* wa_b    = (const float*)d_in[10];
    const float* att     = (const float*)d_in[11];
    const float* bias    = (const float*)d_in[12];
    const int*   ei      = (const int*)d_in[13];

    const int E = in_sizes[13] / 2;
    const int B = E / EPG;
    const int nItems = B * 2;

    const size_t smem1 = (size_t)K1_FLOATS * 4;
    const size_t smem2 = (size_t)K2_FLOATS * 4;
    cudaFuncSetAttribute(mgnn_k1, cudaFuncAttributeMaxDynamicSharedMemorySize, (int)smem1);
    cudaFuncSetAttribute(mgnn_k2, cudaFuncAttributeMaxDynamicSharedMemorySize, (int)smem2);

    const int grid1 = (nItems < K1_GRID) ? nItems : K1_GRID;
    mgnn_k1<<<grid1, TPB, smem1>>>(x, lin1_w, lin1_b, p1_w, p1_b, p2_w, p2_b,
                                   p_bias1, wa_w, wa_b, att, ei, E, nItems);
    mgnn_k2<<<B, TPB, smem2>>>(bias, ei, E, (float*)d_out);
}

// round 17
// speedup vs baseline: 1.5471x; 1.0448x over previous
#include <cuda_runtime.h>
#include <cuda_fp16.h>
#include <cstdint>

#define NPG     100
#define EPG     1600
#define HALF_E  800
#define DIMK    32
#define TPB     256
#define TILE_E  256
#define EPITCH  260
#define EPH     264     // half pitch for EtH
#define XPITCH  33
#define DPITCH  65
#define KSEL    800
#define MAXE    800000
#define K1_GRID 296

typedef unsigned long long ull;

__device__ __half g_ex[(size_t)MAXE * 64];
__device__ __half g_wa[(size_t)MAXE * 32];
__device__ float  g_p [(size_t)MAXE];
__device__ int    g_ctr;   // zero-init; K2 resets for next replay

__device__ __forceinline__ ull dup2(float v) {
    ull r; asm("mov.b64 %0, {%1, %1};" : "=l"(r) : "f"(v)); return r;
}
__device__ __forceinline__ void fma2(ull& acc, ull a, ull b) {
    asm("fma.rn.f32x2 %0, %1, %2, %0;" : "+l"(acc) : "l"(a), "l"(b));
}
__device__ __forceinline__ float2 unp(ull v) {
    float2 f; asm("mov.b64 {%0, %1}, %2;" : "=f"(f.x), "=f"(f.y) : "l"(v)); return f;
}
__device__ __forceinline__ float fsig(float x) {
    return 1.0f / (1.0f + __expf(-x));
}

// ---- K1 SMEM layout (float idx) ----
#define S_XS    0        // 3304
#define S_WG    3304     // 2048  p1_w fp32
#define S_WH    5352     // 1536  (32x96 half: 64 lin1 | 32 wa)
#define S_BL1   6888     // 64
#define S_BWA   6952     // 32
#define S_BP1   6984     // 64
#define S_PB1O  7048     // 64
#define S_WP2   7112     // 64
#define S_PSA   7176     // 800
#define S_ITEM  7976     // 8
#define S_ET    7984     // 260*32 = 8320
#define S_ETH   16304    // 264*32 half = 4224 floats
#define K1_FLOATS 20528

extern "C" __global__ void __launch_bounds__(TPB, 2)
mgnn_k1(const float* __restrict__ x,
        const float* __restrict__ lin1_w, const float* __restrict__ lin1_b,
        const float* __restrict__ p1_w,   const float* __restrict__ p1_b,
        const float* __restrict__ p2_w,   const float* __restrict__ p2_b,
        const float* __restrict__ p_bias1,
        const float* __restrict__ wa_w,   const float* __restrict__ wa_b,
        const float* __restrict__ att,    const int* __restrict__ ei,
        int E, int nItems)
{
    extern __shared__ float sm[];
    float*  xs    = sm + S_XS;
    float*  wG    = sm + S_WG;
    __half* wH    = (__half*)(sm + S_WH);
    float*  bl1S  = sm + S_BL1;
    float*  bwaS  = sm + S_BWA;
    float*  bp1S  = sm + S_BP1;
    float*  pb1oS = sm + S_PB1O;
    float*  wp2S  = sm + S_WP2;
    float*  psA   = sm + S_PSA;
    int*    itemS = (int*)(sm + S_ITEM);
    float*  Et    = sm + S_ET;
    __half* EtH   = (__half*)(sm + S_ETH);

    __shared__ float attS[64];

    const int tid = threadIdx.x;
    const int* srcA = ei;
    const int* tgtA = ei + E;

    // ---- stage weights ONCE per CTA ----
    for (int idx = tid; idx < DIMK * 64; idx += TPB) wG[idx] = p1_w[idx];
    for (int idx = tid; idx < DIMK * 96; idx += TPB) {
        int k = idx / 96, n = idx % 96;
        float w = (n < 64) ? lin1_w[k * 64 + n] : wa_w[k * 32 + (n - 64)];
        wH[idx] = __float2half(w);
    }
    if (tid < 64) {
        bl1S[tid]  = lin1_b[tid];
        bp1S[tid]  = p1_b[tid];
        pb1oS[tid] = p_bias1[tid];
        wp2S[tid]  = p2_w[tid];
        attS[tid]  = att[tid];
    }
    if (tid < 32) bwaS[tid] = wa_b[tid];
    const float p2bias = p2_b[0];

    while (true) {
        if (tid == 0) itemS[0] = atomicAdd(&g_ctr, 1);
        __syncthreads();
        const int item = itemS[0];
        __syncthreads();
        if (item >= nItems) break;

        const int g = item >> 1;
        const int h = item & 1;
        const int nodeBase = g * NPG;
        const int edgeBase = g * EPG + h * HALF_E;

        for (int idx = tid; idx < NPG * DIMK; idx += TPB) {
            int r = idx >> 5, c = idx & 31;
            xs[r * XPITCH + c] = x[(size_t)nodeBase * DIMK + idx];
        }
        for (int i = tid; i < HALF_E; i += TPB) psA[i] = 0.0f;
        __syncthreads();

        for (int tb = 0; tb < HALF_E; tb += TILE_E) {
            const int curE = min(TILE_E, HALF_E - tb);   // 256,256,256,32
            if (tid < curE) {
                int ge = edgeBase + tb + tid;
                int ls = srcA[ge] - nodeBase;
                int lt = tgtA[ge] - nodeBase;
                const float* xt = xs + lt * XPITCH;
                const float* xr = xs + ls * XPITCH;
                #pragma unroll
                for (int k = 0; k < DIMK; k++) {
                    float e = xt[k] * xr[k];
                    Et[k * EPITCH + tid]  = e;
                    EtH[k * EPH + tid]    = __float2half(e);
                }
            }
            __syncthreads();

            const int nEg = curE >> 2;

            // ======== fp16 part: lin1 (64) | wa (32) via HFMA2 ========
            for (int u = tid; u < nEg * 12; u += TPB) {
                const int eg = u % nEg;
                const int cg = u / nEg;
                const int jc = cg * 8;      // 0..88

                __half2 acc[4][4];
                #pragma unroll
                for (int e = 0; e < 4; e++)
                    #pragma unroll
                    for (int q = 0; q < 4; q++)
                        acc[e][q] = __half2half2(__float2half(0.0f));

                const __half* etp = EtH + eg * 4;
                const __half* wp  = wH + jc;
                #pragma unroll 8
                for (int k = 0; k < DIMK; k++) {
                    uint2 av = *(const uint2*)(etp + k * EPH);
                    __half2 a01 = *(__half2*)&av.x;
                    __half2 a23 = *(__half2*)&av.y;
                    __half2 aa0 = __half2half2(__low2half(a01));
                    __half2 aa1 = __half2half2(__high2half(a01));
                    __half2 aa2 = __half2half2(__low2half(a23));
                    __half2 aa3 = __half2half2(__high2half(a23));
                    uint4 bv = *(const uint4*)(wp + k * 96);
                    __half2 b0 = *(__half2*)&bv.x;
                    __half2 b1 = *(__half2*)&bv.y;
                    __half2 b2 = *(__half2*)&bv.z;
                    __half2 b3 = *(__half2*)&bv.w;
                    acc[0][0] = __hfma2(aa0, b0, acc[0][0]); acc[0][1] = __hfma2(aa0, b1, acc[0][1]);
                    acc[0][2] = __hfma2(aa0, b2, acc[0][2]); acc[0][3] = __hfma2(aa0, b3, acc[0][3]);
                    acc[1][0] = __hfma2(aa1, b0, acc[1][0]); acc[1][1] = __hfma2(aa1, b1, acc[1][1]);
                    acc[1][2] = __hfma2(aa1, b2, acc[1][2]); acc[1][3] = __hfma2(aa1, b3, acc[1][3]);
                    acc[2][0] = __hfma2(aa2, b0, acc[2][0]); acc[2][1] = __hfma2(aa2, b1, acc[2][1]);
                    acc[2][2] = __hfma2(aa2, b2, acc[2][2]); acc[2][3] = __hfma2(aa2, b3, acc[2][3]);
                    acc[3][0] = __hfma2(aa3, b0, acc[3][0]); acc[3][1] = __hfma2(aa3, b1, acc[3][1]);
                    acc[3][2] = __hfma2(aa3, b2, acc[3][2]); acc[3][3] = __hfma2(aa3, b3, acc[3][3]);
                }

                const int iiBase = tb + eg * 4;
                if (jc < 64) {
                    #pragma unroll
                    for (int e = 0; e < 4; e++) {
                        unsigned hv[4];
                        #pragma unroll
                        for (int q = 0; q < 4; q++) {
                            float2 t2 = __half22float2(acc[e][q]);
                            float v0 = t2.x + bl1S[jc + 2 * q];
                            float v1 = t2.y + bl1S[jc + 2 * q + 1];
                            float c0 = attS[jc + 2 * q]     * fmaxf(v0, 0.0f);
                            float c1 = attS[jc + 2 * q + 1] * fmaxf(v1, 0.0f);
                            c0 = (c0 > 0.0f) ? c0 : 0.01f * c0;
                            c1 = (c1 > 0.0f) ? c1 : 0.01f * c1;
                            __half2 hh = __floats2half2_rn(__expf(c0), __expf(c1));
                            hv[q] = *(unsigned*)&hh;
                        }
                        uint4 pk; pk.x = hv[0]; pk.y = hv[1]; pk.z = hv[2]; pk.w = hv[3];
                        *(uint4*)(g_ex + (size_t)(edgeBase + iiBase + e) * 64 + jc) = pk;
                    }
                } else {
                    const int jj = jc - 64;
                    #pragma unroll
                    for (int e = 0; e < 4; e++) {
                        unsigned hv[4];
                        #pragma unroll
                        for (int q = 0; q < 4; q++) {
                            float2 t2 = __half22float2(acc[e][q]);
                            __half2 hh = __floats2half2_rn(t2.x + bwaS[jj + 2 * q],
                                                           t2.y + bwaS[jj + 2 * q + 1]);
                            hv[q] = *(unsigned*)&hh;
                        }
                        uint4 pk; pk.x = hv[0]; pk.y = hv[1]; pk.z = hv[2]; pk.w = hv[3];
                        *(uint4*)(g_wa + (size_t)(edgeBase + iiBase + e) * 32 + jj) = pk;
                    }
                }
            }

            // ======== fp32 gate MLP (exact) ========
            for (int u = tid; u < nEg * 8; u += TPB) {
                const int eg = u % nEg;
                const int cg = u / nEg;
                const int jj = cg * 8;

                ull acc[4][4];
                {
                    ulonglong2 b0 = *(const ulonglong2*)(bp1S + jj);
                    ulonglong2 b1 = *(const ulonglong2*)(bp1S + jj + 4);
                    #pragma unroll
                    for (int e = 0; e < 4; e++) {
                        acc[e][0] = b0.x; acc[e][1] = b0.y;
                        acc[e][2] = b1.x; acc[e][3] = b1.y;
                    }
                }
                const float* etp = Et + eg * 4;
                const float* wp  = wG + jj;
                #pragma unroll 8
                for (int k = 0; k < DIMK; k++) {
                    float4 a4 = *(const float4*)(etp + k * EPITCH);
                    ull a0 = dup2(a4.x), a1 = dup2(a4.y), a2 = dup2(a4.z), a3 = dup2(a4.w);
                    ulonglong2 bA = *(const ulonglong2*)(wp + k * 64);
                    ulonglong2 bB = *(const ulonglong2*)(wp + k * 64 + 4);
                    fma2(acc[0][0], a0, bA.x); fma2(acc[0][1], a0, bA.y);
                    fma2(acc[0][2], a0, bB.x); fma2(acc[0][3], a0, bB.y);
                    fma2(acc[1][0], a1, bA.x); fma2(acc[1][1], a1, bA.y);
                    fma2(acc[1][2], a1, bB.x); fma2(acc[1][3], a1, bB.y);
                    fma2(acc[2][0], a2, bA.x); fma2(acc[2][1], a2, bA.y);
                    fma2(acc[2][2], a2, bB.x); fma2(acc[2][3], a2, bB.y);
                    fma2(acc[3][0], a3, bA.x); fma2(acc[3][1], a3, bA.y);
                    fma2(acc[3][2], a3, bB.x); fma2(acc[3][3], a3, bB.y);
                }
                #pragma unroll
                for (int e = 0; e < 4; e++) {
                    float s = 0.0f;
                    #pragma unroll
                    for (int q = 0; q < 4; q++) {
                        float2 v = unp(acc[e][q]);
                        s += (fmaxf(v.x, 0.0f) + pb1oS[jj + 2 * q])     * wp2S[jj + 2 * q];
                        s += (fmaxf(v.y, 0.0f) + pb1oS[jj + 2 * q + 1]) * wp2S[jj + 2 * q + 1];
                    }
                    atomicAdd(&psA[tb + eg * 4 + e], s);
                }
            }
            __syncthreads();
        }

        for (int i = tid; i < HALF_E; i += TPB)
            g_p[edgeBase + i] = fsig(psA[i] + p2bias);
        __syncthreads();
    }
}

// ================= K2: select + gathers (R8 measured-best) =================
#define K2_PS    0
#define K2_DENS  1600
#define K2_INVD  8104
#define K2_BOUT  8204
#define K2_CNT   8268
#define K2_OFFS  8368
#define K2_CUR   8472
#define K2_LIST  8572
#define K2_TIE   10172
#define K2_SCAL  10236
#define K2_UNI   10244
#define K2_FLOATS 13444

extern "C" __global__ void __launch_bounds__(TPB, 4)
mgnn_k2(const float* __restrict__ bias, const int* __restrict__ ei, int E,
        float* __restrict__ out)
{
    extern __shared__ float sm[];
    float* psA   = sm + K2_PS;
    float* dens  = sm + K2_DENS;
    float* invdS = sm + K2_INVD;
    float* boutS = sm + K2_BOUT;
    int*   cnt   = (int*)(sm + K2_CNT);
    int*   offs  = (int*)(sm + K2_OFFS);
    int*   curS  = (int*)(sm + K2_CUR);
    int*   listS = (int*)(sm + K2_LIST);
    int*   tieS  = (int*)(sm + K2_TIE);
    int*   scal  = (int*)(sm + K2_SCAL);
    int*   hist  = (int*)(sm + K2_UNI);
    float* als0  = sm + K2_UNI;
    float* als1  = sm + K2_UNI + EPG;

    const int g        = blockIdx.x;
    const int tid      = threadIdx.x;
    const int nodeBase = g * NPG;
    const int edgeBase = g * EPG;
    const int* tgtA = ei + E;

    if (g == 0 && tid == 0) g_ctr = 0;

    if (tid < 64) boutS[tid] = bias[tid];
    for (int t = tid; t < NPG; t += TPB) cnt[t] = 0;
    for (int i = tid; i < EPG; i += TPB) psA[i] = g_p[edgeBase + i];
    __syncthreads();
    for (int i = tid; i < EPG; i += TPB)
        atomicAdd(&cnt[tgtA[edgeBase + i] - nodeBase], 1);
    __syncthreads();

    if (tid < 32) {
        int base = tid * 4;
        int c0 = 0, c1 = 0, c2 = 0, c3 = 0;
        if (base < NPG) { c0 = cnt[base]; c1 = cnt[base+1]; c2 = cnt[base+2]; c3 = cnt[base+3]; }
        int s = c0 + c1 + c2 + c3;
        int ex = s;
        #pragma unroll
        for (int off = 1; off < 32; off <<= 1) {
            int v = __shfl_up_sync(0xFFFFFFFFu, ex, off);
            if (tid >= off) ex += v;
        }
        ex -= s;
        if (base < NPG) {
            offs[base]     = ex;
            offs[base + 1] = ex + c0;
            offs[base + 2] = ex + c0 + c1;
            offs[base + 3] = ex + c0 + c1 + c2;
            if (base + 4 == NPG) offs[NPG] = ex + s;
        }
    }
    __syncthreads();

    unsigned prefix = 0;
    int target = KSEL;
    for (int b = 3; b >= 0; b--) {
        for (int i = tid; i < 256; i += TPB) hist[i] = 0;
        __syncthreads();
        unsigned maskAbove = (b == 3) ? 0u : (0xFFFFFFFFu << (8 * (b + 1)));
        for (int i = tid; i < EPG; i += TPB) {
            unsigned ub = __float_as_uint(psA[i]);
            if ((ub & maskAbove) == (prefix & maskAbove))
                atomicAdd(&hist[(ub >> (8 * b)) & 255], 1);
        }
        __syncthreads();
        if (tid < 32) {
            const int hi = 255 - 8 * tid;
            int hh[8], s = 0;
            #pragma unroll
            for (int q = 0; q < 8; q++) { hh[q] = hist[hi - q]; s += hh[q]; }
            int ex = s;
            #pragma unroll
            for (int off = 1; off < 32; off <<= 1) {
                int v = __shfl_up_sync(0xFFFFFFFFu, ex, off);
                if (tid >= off) ex += v;
            }
            ex -= s;
            unsigned flags = __ballot_sync(0xFFFFFFFFu, ex + s >= target);
            int sel = (flags != 0u) ? (__ffs(flags) - 1) : 31;
            if (tid == sel) {
                int acc = ex, bin = hi - 7;
                #pragma unroll
                for (int q = 0; q < 8; q++) {
                    if (acc + hh[q] >= target) { bin = hi - q; break; }
                    acc += hh[q];
                }
                scal[0] = (int)(prefix | ((unsigned)bin << (8 * b)));
                scal[1] = target - acc;
            }
        }
        __syncthreads();
        prefix = (unsigned)scal[0];
        target = scal[1];
        __syncthreads();
    }
    const unsigned thrBits = prefix;

    if (tid == 0) { scal[2] = 0; scal[3] = 0; }
    __syncthreads();
    for (int i = tid; i < EPG; i += TPB) {
        unsigned ub = __float_as_uint(psA[i]);
        if (ub > thrBits) { atomicAdd(&scal[2], 1); }
        else if (ub == thrBits) {
            int pos = atomicAdd(&scal[3], 1);
            if (pos < 64) tieS[pos] = i;
        } else {
            psA[i] = 0.0f;
        }
    }
    __syncthreads();
    if (tid == 0) {
        int cGt = scal[2];
        int tn = min(scal[3], 64);
        int need = KSEL - cGt;
        for (int a = 1; a < tn; a++) {
            int v = tieS[a]; int bb = a - 1;
            while (bb >= 0 && tieS[bb] > v) { tieS[bb + 1] = tieS[bb]; bb--; }
            tieS[bb + 1] = v;
        }
        for (int r = need; r < tn; r++) if (r >= 0) psA[tieS[r]] = 0.0f;
    }
    __syncthreads();

    for (int t = tid; t < NPG; t += TPB) {
        curS[t] = offs[t];
        invdS[t] = 1.0f / fmaxf((float)cnt[t], 1.0f);
    }
    __syncthreads();
    for (int i = tid; i < EPG; i += TPB) {
        int lt = tgtA[edgeBase + i] - nodeBase;
        int pos = atomicAdd(&curS[lt], 1);
        listS[pos] = i;
    }
    __syncthreads();

    for (int u = tid; u < NPG * 8; u += TPB) {
        int t = u >> 3, ch = u & 7;
        int s0 = offs[t], s1 = offs[t + 1];
        float a[8] = {0, 0, 0, 0, 0, 0, 0, 0};
        int idx = s0;
        for (; idx + 3 < s1; idx += 4) {
            int i0 = listS[idx], i1 = listS[idx+1], i2 = listS[idx+2], i3 = listS[idx+3];
            uint4 h0 = *(const uint4*)(g_ex + (size_t)(edgeBase + i0) * 64 + ch * 8);
            uint4 h1 = *(const uint4*)(g_ex + (size_t)(edgeBase + i1) * 64 + ch * 8);
            uint4 h2 = *(const uint4*)(g_ex + (size_t)(edgeBase + i2) * 64 + ch * 8);
            uint4 h3 = *(const uint4*)(g_ex + (size_t)(edgeBase + i3) * 64 + ch * 8);
            const uint4* hs[4] = {&h0, &h1, &h2, &h3};
            #pragma unroll
            for (int r = 0; r < 4; r++) {
                float2 v0 = __half22float2(*(__half2*)&hs[r]->x);
                float2 v1 = __half22float2(*(__half2*)&hs[r]->y);
                float2 v2 = __half22float2(*(__half2*)&hs[r]->z);
                float2 v3 = __half22float2(*(__half2*)&hs[r]->w);
                a[0] += v0.x; a[1] += v0.y; a[2] += v1.x; a[3] += v1.y;
                a[4] += v2.x; a[5] += v2.y; a[6] += v3.x; a[7] += v3.y;
            }
        }
        for (; idx < s1; idx++) {
            int i = listS[idx];
            uint4 h4 = *(const uint4*)(g_ex + (size_t)(edgeBase + i) * 64 + ch * 8);
            float2 v0 = __half22float2(*(__half2*)&h4.x);
            float2 v1 = __half22float2(*(__half2*)&h4.y);
            float2 v2 = __half22float2(*(__half2*)&h4.z);
            float2 v3 = __half22float2(*(__half2*)&h4.w);
            a[0] += v0.x; a[1] += v0.y; a[2] += v1.x; a[3] += v1.y;
            a[4] += v2.x; a[5] += v2.y; a[6] += v3.x; a[7] += v3.y;
        }
        #pragma unroll
        for (int j = 0; j < 8; j++)
            dens[t * DPITCH + ch * 8 + j] = 1.0f / (a[j] + 1e-16f);
    }
    __syncthreads();

    for (int i = tid; i < EPG; i += TPB) {
        int lt = tgtA[edgeBase + i] - nodeBase;
        const float* invd = dens + lt * DPITCH;
        const uint4* exr = (const uint4*)(g_ex + (size_t)(edgeBase + i) * 64);
        float a0 = 0.0f, a1 = 0.0f;
        #pragma unroll
        for (int q = 0; q < 8; q++) {
            uint4 h4 = exr[q];
            float2 v0 = __half22float2(*(__half2*)&h4.x);
            float2 v1 = __half22float2(*(__half2*)&h4.y);
            float2 v2 = __half22float2(*(__half2*)&h4.z);
            float2 v3 = __half22float2(*(__half2*)&h4.w);
            const float* iv = invd + q * 8;
            float s = v0.x * iv[0] + v0.y * iv[1] + v1.x * iv[2] + v1.y * iv[3]
                    + v2.x * iv[4] + v2.y * iv[5] + v3.x * iv[6] + v3.y * iv[7];
            if (q < 4) a0 += s; else a1 += s;
        }
        float pv = psA[i];
        als0[i] = a0 * pv;
        als1[i] = a1 * pv;
    }
    __syncthreads();

    for (int u = tid; u < NPG * 8; u += TPB) {
        int t = u >> 3, ch = u & 7;
        const float* als = (ch >= 4) ? als1 : als0;
        int wcb = (ch & 3) * 8;
        int s0 = offs[t], s1 = offs[t + 1];
        float a[8] = {0, 0, 0, 0, 0, 0, 0, 0};
        int idx = s0;
        for (; idx + 3 < s1; idx += 4) {
            int i0 = listS[idx], i1 = listS[idx+1], i2 = listS[idx+2], i3 = listS[idx+3];
            uint4 h0 = *(const uint4*)(g_wa + (size_t)(edgeBase + i0) * 32 + wcb);
            uint4 h1 = *(const uint4*)(g_wa + (size_t)(edgeBase + i1) * 32 + wcb);
            uint4 h2 = *(const uint4*)(g_wa + (size_t)(edgeBase + i2) * 32 + wcb);
            uint4 h3 = *(const uint4*)(g_wa + (size_t)(edgeBase + i3) * 32 + wcb);
            float aps[4] = {als[i0], als[i1], als[i2], als[i3]};
            const uint4* hs[4] = {&h0, &h1, &h2, &h3};
            #pragma unroll
            for (int r = 0; r < 4; r++) {
                float2 w0 = __half22float2(*(__half2*)&hs[r]->x);
                float2 w1 = __half22float2(*(__half2*)&hs[r]->y);
                float2 w2 = __half22float2(*(__half2*)&hs[r]->z);
                float2 w3 = __half22float2(*(__half2*)&hs[r]->w);
                float ap = aps[r];
                a[0] += fsig(w0.x * ap); a[1] += fsig(w0.y * ap);
                a[2] += fsig(w1.x * ap); a[3] += fsig(w1.y * ap);
                a[4] += fsig(w2.x * ap); a[5] += fsig(w2.y * ap);
                a[6] += fsig(w3.x * ap); a[7] += fsig(w3.y * ap);
            }
        }
        for (; idx < s1; idx++) {
            int i = listS[idx];
            float ap = als[i];
            uint4 h4 = *(const uint4*)(g_wa + (size_t)(edgeBase + i) * 32 + wcb);
            float2 w0 = __half22float2(*(__half2*)&h4.x);
            float2 w1 = __half22float2(*(__half2*)&h4.y);
            float2 w2 = __half22float2(*(__half2*)&h4.z);
            float2 w3 = __half22float2(*(__half2*)&h4.w);
            a[0] += fsig(w0.x * ap); a[1] += fsig(w0.y * ap);
            a[2] += fsig(w1.x * ap); a[3] += fsig(w1.y * ap);
            a[4] += fsig(w2.x * ap); a[5] += fsig(w2.y * ap);
            a[6] += fsig(w3.x * ap); a[7] += fsig(w3.y * ap);
        }
        const float idg = invdS[t];
        const int ob = (nodeBase + t) * 64 + ch * 8;
        float4 o0, o1;
        o0.x = a[0] * idg + boutS[ch * 8 + 0];
        o0.y = a[1] * idg + boutS[ch * 8 + 1];
        o0.z = a[2] * idg + boutS[ch * 8 + 2];
        o0.w = a[3] * idg + boutS[ch * 8 + 3];
        o1.x = a[4] * idg + boutS[ch * 8 + 4];
        o1.y = a[5] * idg + boutS[ch * 8 + 5];
        o1.z = a[6] * idg + boutS[ch * 8 + 6];
        o1.w = a[7] * idg + boutS[ch * 8 + 7];
        *(float4*)(out + ob)     = o0;
        *(float4*)(out + ob + 4) = o1;
    }
}

extern "C" void kernel_launch(void* const* d_in, const int* in_sizes, int n_in,
                              void* d_out, int out_size)
{
    const float* x       = (const float*)d_in[0];
    const float* lin1_w  = (const float*)d_in[1];
    const float* lin1_b  = (const float*)d_in[2];
    const float* p1_w    = (const float*)d_in[3];
    const float* p1_b    = (const float*)d_in[4];
    const float* p2_w    = (const float*)d_in[5];
    const float* p2_b    = (const float*)d_in[6];
    const float* p_bias1 = (const float*)d_in[7];
    const float* wa_w    = (const float*)d_in[9];
    const float* wa_b    = (const float*)d_in[10];
    const float* att     = (const float*)d_in[11];
    const float* bias    = (const float*)d_in[12];
    const int*   ei      = (const int*)d_in[13];

    const int E = in_sizes[13] / 2;
    const int B = E / EPG;
    const int nItems = B * 2;

    const size_t smem1 = (size_t)K1_FLOATS * 4;
    const size_t smem2 = (size_t)K2_FLOATS * 4;
    cudaFuncSetAttribute(mgnn_k1, cudaFuncAttributeMaxDynamicSharedMemorySize, (int)smem1);
    cudaFuncSetAttribute(mgnn_k2, cudaFuncAttributeMaxDynamicSharedMemorySize, (int)smem2);

    const int grid1 = (nItems < K1_GRID) ? nItems : K1_GRID;
    mgnn_k1<<<grid1, TPB, smem1>>>(x, lin1_w, lin1_b, p1_w, p1_b, p2_w, p2_b,
                                   p_bias1, wa_w, wa_b, att, ei, E, nItems);
    mgnn_k2<<<B, TPB, smem2>>>(bias, ei, E, (float*)d_out);
}